// round 6
// baseline (speedup 1.0000x reference)
#include <cuda_runtime.h>
#include <cuda_bf16.h>

#define HID  256
#define NS   16       // sampling points
#define NB   16       // batch
#define NQ   300      // queries
#define NLQ  3        // only queries 0..2 are ever gathered (ref_levels in [0,3))
#define W0   100      // level-0 width
#define H0   100      // level-0 height
#define SROWS 8       // s-rows per block (2 blocks cover S=16)

// Scratch: scaled tanh offsets for the 768 active rows: [B, 3, S, 4]
__device__ float d_off[NB * NLQ * NS * 4];

// ---------------------------------------------------------------------------
// Kernel 1: bilinear sample level-0 features for (b, qi in {0,1,2}, s), run the
// 2-layer MLP, store 0.077*tanh(off) into d_off.
// Grid: NB*NLQ*2 = 96 blocks, 256 threads.
// ---------------------------------------------------------------------------
__global__ __launch_bounds__(256)
void k_sample_mlp(const float* __restrict__ ref_polys,
                  const float* __restrict__ memory,
                  const float* __restrict__ w1,
                  const float* __restrict__ b1,
                  const float* __restrict__ w2,
                  const float* __restrict__ b2)
{
    const int blk   = blockIdx.x;
    const int shalf = blk & 1;
    const int qi    = (blk >> 1) % NLQ;
    const int b     = blk / (2 * NLQ);
    const int bq3   = b * NLQ + qi;
    const int tid   = threadIdx.x;

    __shared__ float g[SROWS][HID];        // sampled features (row s, chan c)
    __shared__ float h1s[SROWS][HID + 4];  // +4 pad: conflict-free strided reads
    __shared__ float spxy[SROWS][2];

    // --- sampling locations (Horner, t = s/15) ---
    const float* rp = ref_polys + (b * NQ + qi) * 8;
    if (tid < SROWS) {
        int s = shalf * SROWS + tid;
        float t = (float)s * (1.0f / 15.0f);
        float px = 2.0f * (fmaf(fmaf(fmaf(rp[0], t, rp[1]), t, rp[2]), t, rp[3]) - 0.5f);
        float py = 2.0f * (fmaf(fmaf(fmaf(rp[4], t, rp[5]), t, rp[6]), t, rp[7]) - 0.5f);
        spxy[tid][0] = px;
        spxy[tid][1] = py;
    }
    __syncthreads();

    // --- bilinear gather (align_corners=False, zero padding), level 0 only ---
    const float* mb = memory + (size_t)b * 13125 * HID;   // level-0 starts at 0
    #pragma unroll
    for (int sl = 0; sl < SROWS; sl++) {
        float x = (spxy[sl][0] + 1.0f) * (0.5f * (float)W0) - 0.5f;
        float y = (spxy[sl][1] + 1.0f) * (0.5f * (float)H0) - 0.5f;
        float x0f = floorf(x), y0f = floorf(y);
        int x0 = (int)x0f, y0 = (int)y0f;
        int x1 = x0 + 1,   y1 = y0 + 1;
        float wx1 = x - x0f, wx0 = 1.0f - wx1;
        float wy1 = y - y0f, wy0 = 1.0f - wy1;
        bool vx0 = (x0 >= 0) && (x0 < W0);
        bool vx1 = (x1 >= 0) && (x1 < W0);
        bool vy0 = (y0 >= 0) && (y0 < H0);
        bool vy1 = (y1 >= 0) && (y1 < H0);
        float acc = 0.0f;
        if (vx0 && vy0) acc = fmaf(__ldg(&mb[(y0 * W0 + x0) * HID + tid]), wx0 * wy0, acc);
        if (vx1 && vy0) acc = fmaf(__ldg(&mb[(y0 * W0 + x1) * HID + tid]), wx1 * wy0, acc);
        if (vx0 && vy1) acc = fmaf(__ldg(&mb[(y1 * W0 + x0) * HID + tid]), wx0 * wy1, acc);
        if (vx1 && vy1) acc = fmaf(__ldg(&mb[(y1 * W0 + x1) * HID + tid]), wx1 * wy1, acc);
        g[sl][tid] = acc;
    }
    __syncthreads();

    // --- layer 1: h1[s][c] = tanh(sum_k g[s][k] * w1[k][c] + b1[c]) ---
    // thread = column c; 8-row register tile; k stepped by 4 with float4 LDS
    // of g (broadcast, conflict-free) to cut LDS issue count 4x.
    float acc[SROWS];
    #pragma unroll
    for (int i = 0; i < SROWS; i++) acc[i] = 0.0f;

    #pragma unroll 2
    for (int k = 0; k < HID; k += 4) {
        float w0v = __ldg(&w1[(k + 0) * HID + tid]);
        float w1v = __ldg(&w1[(k + 1) * HID + tid]);
        float w2v = __ldg(&w1[(k + 2) * HID + tid]);
        float w3v = __ldg(&w1[(k + 3) * HID + tid]);
        #pragma unroll
        for (int i = 0; i < SROWS; i++) {
            float4 gv = *reinterpret_cast<const float4*>(&g[i][k]);
            acc[i] = fmaf(gv.x, w0v, acc[i]);
            acc[i] = fmaf(gv.y, w1v, acc[i]);
            acc[i] = fmaf(gv.z, w2v, acc[i]);
            acc[i] = fmaf(gv.w, w3v, acc[i]);
        }
    }
    float bb = b1[tid];
    #pragma unroll
    for (int i = 0; i < SROWS; i++)
        h1s[i][tid] = tanhf(acc[i] + bb);
    __syncthreads();

    // --- layer 2: off[s][j] = sum_c h1[s][c] * w2[c][j] + b2[j]  (32 outputs) ---
    // 8 lanes per output, shfl-tree reduce.
    int out_id = tid >> 3;        // 0..31
    int part   = tid & 7;
    int sl     = out_id >> 2;     // 0..7
    int j      = out_id & 3;
    float a2 = 0.0f;
    #pragma unroll 4
    for (int c = part; c < HID; c += 8)
        a2 = fmaf(h1s[sl][c], __ldg(&w2[c * 4 + j]), a2);
    #pragma unroll
    for (int d = 4; d > 0; d >>= 1)
        a2 += __shfl_down_sync(0xffffffffu, a2, d);
    if (part == 0) {
        int s = shalf * SROWS + sl;
        d_off[(bq3 * NS + s) * 4 + j] = 0.077f * tanhf(a2 + b2[j]);
    }
}

// ---------------------------------------------------------------------------
// Kernel 2: out[b,q,s,np,k] = d_off[b, ref_levels[b,q], s, np*2+k] + sp[b,q,s,k]
// One thread per (b,q,s); float4 load of d_off row, float4 store covers (np,k).
// ---------------------------------------------------------------------------
__global__ __launch_bounds__(256)
void k_out(const float* __restrict__ ref_polys,
           const int*   __restrict__ ref_levels,
           float*       __restrict__ out)
{
    int idx = blockIdx.x * blockDim.x + threadIdx.x;   // over B*Q*S
    if (idx >= NB * NQ * NS) return;
    int s  = idx & (NS - 1);
    int bq = idx >> 4;                                  // b*NQ + q
    int b  = bq / NQ;

    const float* rp = ref_polys + bq * 8;
    float t = (float)s * (1.0f / 15.0f);
    float px = 2.0f * (fmaf(fmaf(fmaf(__ldg(&rp[0]), t, __ldg(&rp[1])), t, __ldg(&rp[2])), t, __ldg(&rp[3])) - 0.5f);
    float py = 2.0f * (fmaf(fmaf(fmaf(__ldg(&rp[4]), t, __ldg(&rp[5])), t, __ldg(&rp[6])), t, __ldg(&rp[7])) - 0.5f);

    int rl = __ldg(&ref_levels[bq]);
    rl = min(max(rl, 0), NLQ - 1);

    float4 o = *reinterpret_cast<const float4*>(
        &d_off[((b * NLQ + rl) * NS + s) * 4]);
    float4 r;
    r.x = o.x + px;
    r.y = o.y + py;
    r.z = o.z + px;
    r.w = o.w + py;
    reinterpret_cast<float4*>(out)[idx] = r;
}

// ---------------------------------------------------------------------------
extern "C" void kernel_launch(void* const* d_in, const int* in_sizes, int n_in,
                              void* d_out, int out_size)
{
    const float* ref_polys  = (const float*)d_in[0];
    const float* memory     = (const float*)d_in[1];
    const float* w1         = (const float*)d_in[2];
    const float* b1         = (const float*)d_in[3];
    const float* w2         = (const float*)d_in[4];
    const float* b2         = (const float*)d_in[5];
    const int*   ref_levels = (const int*)d_in[6];
    float* out = (float*)d_out;

    k_sample_mlp<<<NB * NLQ * 2, 256>>>(ref_polys, memory, w1, b1, w2, b2);

    int n = NB * NQ * NS;
    k_out<<<(n + 255) / 256, 256>>>(ref_polys, ref_levels, out);
}

// round 7
// speedup vs baseline: 1.3067x; 1.3067x over previous
#include <cuda_runtime.h>
#include <cuda_bf16.h>

#define HID  256
#define NS   16       // sampling points
#define NB   16       // batch
#define NQ   300      // queries
#define NLQ  3        // only queries 0..2 are ever gathered (ref_levels in [0,3))
#define W0   100      // level-0 width
#define H0   100      // level-0 height
#define SROWS 8       // s-rows per block (2 blocks cover S=16)

// Scratch: scaled tanh offsets for the 768 active rows: [B, 3, S, 4]
__device__ float d_off[NB * NLQ * NS * 4];

// ---------------------------------------------------------------------------
// Kernel 1: bilinear sample level-0 features for (b, qi in {0,1,2}, s), run the
// 2-layer MLP, store 0.077*tanh(off) into d_off.
// Grid: NB*NLQ*2 = 96 blocks, 256 threads.
// ---------------------------------------------------------------------------
__global__ __launch_bounds__(256)
void k_sample_mlp(const float* __restrict__ ref_polys,
                  const float* __restrict__ memory,
                  const float* __restrict__ w1,
                  const float* __restrict__ b1,
                  const float* __restrict__ w2,
                  const float* __restrict__ b2)
{
    const int blk   = blockIdx.x;
    const int shalf = blk & 1;
    const int qi    = (blk >> 1) % NLQ;
    const int b     = blk / (2 * NLQ);
    const int bq3   = b * NLQ + qi;
    const int tid   = threadIdx.x;

    __shared__ float g[SROWS][HID];        // sampled features (row s, chan c)
    __shared__ float h1s[SROWS][HID + 4];  // +4 pad: conflict-free strided reads
    __shared__ float spxy[SROWS][2];

    // --- sampling locations (Horner, t = s/15) ---
    const float4* rp4 = reinterpret_cast<const float4*>(ref_polys + (b * NQ + qi) * 8);
    if (tid < SROWS) {
        int s = shalf * SROWS + tid;
        float t = (float)s * (1.0f / 15.0f);
        float4 cx = __ldg(rp4);
        float4 cy = __ldg(rp4 + 1);
        spxy[tid][0] = 2.0f * (fmaf(fmaf(fmaf(cx.x, t, cx.y), t, cx.z), t, cx.w) - 0.5f);
        spxy[tid][1] = 2.0f * (fmaf(fmaf(fmaf(cy.x, t, cy.y), t, cy.z), t, cy.w) - 0.5f);
    }
    __syncthreads();

    // --- bilinear gather (align_corners=False, zero padding), level 0 only ---
    const float* mb = memory + (size_t)b * 13125 * HID;   // level-0 starts at 0
    #pragma unroll
    for (int sl = 0; sl < SROWS; sl++) {
        float x = (spxy[sl][0] + 1.0f) * (0.5f * (float)W0) - 0.5f;
        float y = (spxy[sl][1] + 1.0f) * (0.5f * (float)H0) - 0.5f;
        float x0f = floorf(x), y0f = floorf(y);
        int x0 = (int)x0f, y0 = (int)y0f;
        int x1 = x0 + 1,   y1 = y0 + 1;
        float wx1 = x - x0f, wx0 = 1.0f - wx1;
        float wy1 = y - y0f, wy0 = 1.0f - wy1;
        bool vx0 = (x0 >= 0) && (x0 < W0);
        bool vx1 = (x1 >= 0) && (x1 < W0);
        bool vy0 = (y0 >= 0) && (y0 < H0);
        bool vy1 = (y1 >= 0) && (y1 < H0);
        float acc = 0.0f;
        if (vx0 && vy0) acc = fmaf(__ldg(&mb[(y0 * W0 + x0) * HID + tid]), wx0 * wy0, acc);
        if (vx1 && vy0) acc = fmaf(__ldg(&mb[(y0 * W0 + x1) * HID + tid]), wx1 * wy0, acc);
        if (vx0 && vy1) acc = fmaf(__ldg(&mb[(y1 * W0 + x0) * HID + tid]), wx0 * wy1, acc);
        if (vx1 && vy1) acc = fmaf(__ldg(&mb[(y1 * W0 + x1) * HID + tid]), wx1 * wy1, acc);
        g[sl][tid] = acc;
    }
    __syncthreads();

    // --- layer 1: h1[s][c] = tanh(sum_k g[s][k] * w1[k][c] + b1[c]) ---
    // thread = column c; 8-row register tile; float4 broadcast-LDS of g.
    // w1 rows are software-pipelined 4 quads deep (16 LDGs in flight per
    // thread) so the ~234-cyc L2 latency is covered by the 256 cyc of FFMA
    // issue per 4 quads at 8 warps/SM.
    float acc[SROWS];
    #pragma unroll
    for (int i = 0; i < SROWS; i++) acc[i] = 0.0f;

    float wbuf[4][4];
    #pragma unroll
    for (int p = 0; p < 4; p++)
        #pragma unroll
        for (int j = 0; j < 4; j++)
            wbuf[p][j] = __ldg(&w1[(p * 4 + j) * HID + tid]);

    #pragma unroll 4
    for (int kq = 0; kq < HID / 4; kq++) {
        const int k = kq * 4;
        const int slot = kq & 3;
        float w0v = wbuf[slot][0];
        float w1v = wbuf[slot][1];
        float w2v = wbuf[slot][2];
        float w3v = wbuf[slot][3];
        if (kq + 4 < HID / 4) {
            #pragma unroll
            for (int j = 0; j < 4; j++)
                wbuf[slot][j] = __ldg(&w1[((kq + 4) * 4 + j) * HID + tid]);
        }
        #pragma unroll
        for (int i = 0; i < SROWS; i++) {
            float4 gv = *reinterpret_cast<const float4*>(&g[i][k]);
            acc[i] = fmaf(gv.x, w0v, acc[i]);
            acc[i] = fmaf(gv.y, w1v, acc[i]);
            acc[i] = fmaf(gv.z, w2v, acc[i]);
            acc[i] = fmaf(gv.w, w3v, acc[i]);
        }
    }
    float bb = b1[tid];
    #pragma unroll
    for (int i = 0; i < SROWS; i++)
        h1s[i][tid] = tanhf(acc[i] + bb);
    __syncthreads();

    // --- layer 2: off[s][j] = sum_c h1[s][c] * w2[c][j] + b2[j]  (32 outputs) ---
    // 8 lanes per output, shfl-tree reduce.
    int out_id = tid >> 3;        // 0..31
    int part   = tid & 7;
    int sl     = out_id >> 2;     // 0..7
    int j      = out_id & 3;
    float a2 = 0.0f;
    #pragma unroll 4
    for (int c = part; c < HID; c += 8)
        a2 = fmaf(h1s[sl][c], __ldg(&w2[c * 4 + j]), a2);
    #pragma unroll
    for (int d = 4; d > 0; d >>= 1)
        a2 += __shfl_down_sync(0xffffffffu, a2, d);
    if (part == 0) {
        int s = shalf * SROWS + sl;
        d_off[(bq3 * NS + s) * 4 + j] = 0.077f * tanhf(a2 + b2[j]);
    }
}

// ---------------------------------------------------------------------------
// Kernel 2: out[b,q,s,np,k] = d_off[b, ref_levels[b,q], s, np*2+k] + sp[b,q,s,k]
// One thread per (b,q,s); rp via 2x LDG.128; float4 d_off load; float4 store.
// ---------------------------------------------------------------------------
__global__ __launch_bounds__(256)
void k_out(const float* __restrict__ ref_polys,
           const int*   __restrict__ ref_levels,
           float*       __restrict__ out)
{
    int idx = blockIdx.x * blockDim.x + threadIdx.x;   // over B*Q*S
    if (idx >= NB * NQ * NS) return;
    int s  = idx & (NS - 1);
    int bq = idx >> 4;                                  // b*NQ + q
    int b  = bq / NQ;

    const float4* rp4 = reinterpret_cast<const float4*>(ref_polys + bq * 8);
    float4 cx = __ldg(rp4);
    float4 cy = __ldg(rp4 + 1);
    int rl = __ldg(&ref_levels[bq]);
    rl = min(max(rl, 0), NLQ - 1);

    float t = (float)s * (1.0f / 15.0f);
    float px = 2.0f * (fmaf(fmaf(fmaf(cx.x, t, cx.y), t, cx.z), t, cx.w) - 0.5f);
    float py = 2.0f * (fmaf(fmaf(fmaf(cy.x, t, cy.y), t, cy.z), t, cy.w) - 0.5f);

    float4 o = *reinterpret_cast<const float4*>(
        &d_off[((b * NLQ + rl) * NS + s) * 4]);
    float4 r;
    r.x = o.x + px;
    r.y = o.y + py;
    r.z = o.z + px;
    r.w = o.w + py;
    reinterpret_cast<float4*>(out)[idx] = r;
}

// ---------------------------------------------------------------------------
extern "C" void kernel_launch(void* const* d_in, const int* in_sizes, int n_in,
                              void* d_out, int out_size)
{
    const float* ref_polys  = (const float*)d_in[0];
    const float* memory     = (const float*)d_in[1];
    const float* w1         = (const float*)d_in[2];
    const float* b1         = (const float*)d_in[3];
    const float* w2         = (const float*)d_in[4];
    const float* b2         = (const float*)d_in[5];
    const int*   ref_levels = (const int*)d_in[6];
    float* out = (float*)d_out;

    k_sample_mlp<<<NB * NLQ * 2, 256>>>(ref_polys, memory, w1, b1, w2, b2);

    int n = NB * NQ * NS;
    k_out<<<(n + 255) / 256, 256>>>(ref_polys, ref_levels, out);
}